// round 9
// baseline (speedup 1.0000x reference)
#include <cuda_runtime.h>

#define Bd 8
#define Nd 2048
#define F_IN 256
#define F_OUT 64
#define ALPHA 0.2f

#define TI 64
#define TJ 64
#define SPLIT 2
#define JPB (Nd / SPLIT)   // 1024 j's per block
#define PST 68             // smem row stride (floats), 16B-aligned

typedef unsigned long long ull;

// ---- packed f32x2 helpers (sm_103a FFMA2: 2x fp32 FMA throughput) ----
__device__ __forceinline__ void fma2(ull& d, ull a, ull b) {
    asm("fma.rn.f32x2 %0, %1, %2, %0;" : "+l"(d) : "l"(a), "l"(b));
}
__device__ __forceinline__ ull pack2(float x) {
    ull r; asm("mov.b64 %0, {%1, %1};" : "=l"(r) : "f"(x)); return r;
}
__device__ __forceinline__ void unpack2(float& lo, float& hi, ull v) {
    asm("mov.b64 {%0, %1}, %2;" : "=f"(lo), "=f"(hi) : "l"(v));
}

// ---- scratch (__device__ globals; allocation-free rule) ----
__device__ __align__(16) float g_Wh[Bd * Nd * F_OUT];            // 4 MB
__device__ __align__(16) float g_es[Bd * Nd];
__device__ __align__(16) float g_ed[Bd * Nd];
__device__ __align__(16) float g_pacc[SPLIT * Bd * Nd * F_OUT];  // 8 MB partials
__device__ __align__(16) float g_prs[SPLIT * Bd * Nd];           // partial rowsums

// ---------------------------------------------------------------------------
// Kernel 1: Wh = h @ W, e_src = Wh.a1, e_dst = Wh.a2.
// Tiled GEMM: block = 64 rows x 64 cols, 256 threads, micro-tile 2 rows x
// 8 cols per thread = 8 independent FFMA2 chains (vs 2 before -> latency-
// bound no more). k staged in chunks of 32.
// ---------------------------------------------------------------------------
__global__ __launch_bounds__(256) void wh_kernel(const float* __restrict__ h,
                                                 const float* __restrict__ W,
                                                 const float* __restrict__ a) {
    __shared__ float hs[64][36];   // 64 rows x 32-k chunk (pad 4)
    __shared__ float Ws[32][72];   // 32-k chunk x 64 cols (pad 8)

    int t    = threadIdx.x;
    int row0 = blockIdx.x * 64;
    int colg = t & 7;              // 8 col-groups of 8 cols
    int rp   = t >> 3;             // 0..31 -> rows rp*2, rp*2+1

    const float4* h4 = (const float4*)h;   // [row][64]
    const float4* W4 = (const float4*)W;   // [F_IN][16]

    ull acc[2][4] = {};            // 2 rows x 8 cols (4 f32x2 pairs each)

    for (int c = 0; c < 8; c++) {  // F_IN in chunks of 32
        __syncthreads();
#pragma unroll
        for (int q = 0; q < 2; q++) {      // stage h chunk: 512 float4
            int idx = t * 2 + q;
            int r = idx >> 3, kq = idx & 7;
            *(float4*)&hs[r][kq * 4] = h4[(size_t)(row0 + r) * 64 + c * 8 + kq];
        }
#pragma unroll
        for (int q = 0; q < 2; q++) {      // stage W chunk: 512 float4
            int idx = t * 2 + q;
            int k = idx >> 4, cq = idx & 15;
            *(float4*)&Ws[k][cq * 4] = W4[(size_t)(c * 32 + k) * 16 + cq];
        }
        __syncthreads();
#pragma unroll
        for (int k = 0; k < 32; k++) {
            ulonglong2 w0 = *(const ulonglong2*)&Ws[k][colg * 8];
            ulonglong2 w1 = *(const ulonglong2*)&Ws[k][colg * 8 + 4];
            ull hp0 = pack2(hs[rp * 2 + 0][k]);
            ull hp1 = pack2(hs[rp * 2 + 1][k]);
            fma2(acc[0][0], hp0, w0.x); fma2(acc[0][1], hp0, w0.y);
            fma2(acc[0][2], hp0, w1.x); fma2(acc[0][3], hp0, w1.y);
            fma2(acc[1][0], hp1, w0.x); fma2(acc[1][1], hp1, w0.y);
            fma2(acc[1][2], hp1, w1.x); fma2(acc[1][3], hp1, w1.y);
        }
    }

    // a-vector slices for this col-group
    float a1s[8], a2s[8];
#pragma unroll
    for (int q = 0; q < 2; q++) {
        float4 v1 = ((const float4*)a)[colg * 2 + q];
        float4 v2 = ((const float4*)a)[16 + colg * 2 + q];
        a1s[q * 4 + 0] = v1.x; a1s[q * 4 + 1] = v1.y; a1s[q * 4 + 2] = v1.z; a1s[q * 4 + 3] = v1.w;
        a2s[q * 4 + 0] = v2.x; a2s[q * 4 + 1] = v2.y; a2s[q * 4 + 2] = v2.z; a2s[q * 4 + 3] = v2.w;
    }

#pragma unroll
    for (int m = 0; m < 2; m++) {
        int row = row0 + rp * 2 + m;
        float w[8];
        unpack2(w[0], w[1], acc[m][0]); unpack2(w[2], w[3], acc[m][1]);
        unpack2(w[4], w[5], acc[m][2]); unpack2(w[6], w[7], acc[m][3]);
        float4 o0 = make_float4(w[0], w[1], w[2], w[3]);
        float4 o1 = make_float4(w[4], w[5], w[6], w[7]);
        *(float4*)(g_Wh + (size_t)row * F_OUT + colg * 8)     = o0;
        *(float4*)(g_Wh + (size_t)row * F_OUT + colg * 8 + 4) = o1;

        float p = 0.f, q = 0.f;
#pragma unroll
        for (int u = 0; u < 8; u++) { p += w[u] * a1s[u]; q += w[u] * a2s[u]; }
        // reduce over the 8 col-groups (8 consecutive lanes)
#pragma unroll
        for (int off = 4; off > 0; off >>= 1) {
            p += __shfl_xor_sync(0xFFFFFFFFu, p, off);
            q += __shfl_xor_sync(0xFFFFFFFFu, q, off);
        }
        if (colg == 0) {
            g_es[row] = p;
            g_ed[row] = q;
        }
    }
}

// ---------------------------------------------------------------------------
// Kernel 2: fused attention + aggregation, split-K over j (2-way).
// grid (N/TI, B, SPLIT), 256 threads. P tile stored TRANSPOSED+swizzled in
// smem so both GEMM operands are LDS.128; 4x4 micro-tile via FFMA2.
// adj tile for the NEXT j0 is prefetched into registers right after the
// current P tile is built, so the GEMM covers the ~600cyc DRAM latency.
// Softmax needs no max-subtraction: scores bounded ~10.
// ---------------------------------------------------------------------------
__global__ __launch_bounds__(256, 4) void gat_kernel(const int* __restrict__ adj) {
    __shared__ float PsT[TJ][PST];
    __shared__ float Whs[TJ][PST];
    __shared__ float es_s[TI];
    __shared__ float ed_s[TJ];
    __shared__ float rowsum[TI];

    int t     = threadIdx.x;
    int b     = blockIdx.y;
    int i0    = blockIdx.x * TI;
    int split = blockIdx.z;
    int jbase = split * JPB;
    int jend  = jbase + JPB;

    if (t < TI) rowsum[t] = 0.f;
    if (t < 16) ((float4*)es_s)[t] = ((const float4*)(g_es + (size_t)b * Nd + i0))[t];
    __syncthreads();

    int pi = t >> 2;
    int jq = t & 3;
    float esi = es_s[pi];

    int ty = t >> 4;
    int tx = t & 15;
    ull acc[4][2] = {};

    const float* Whb  = g_Wh + (size_t)b * Nd * F_OUT;
    const float* edb  = g_ed + (size_t)b * Nd;
    const int4*  arow = (const int4*)(adj + (size_t)b * Nd * Nd + (size_t)(i0 + pi) * Nd);

    int lr = t >> 2;
    int lp = t & 3;

    // prefetch adj for the first tile
    int4 av[4];
#pragma unroll
    for (int q = 0; q < 4; q++) av[q] = arow[(jbase >> 2) + jq * 4 + q];

    for (int j0 = jbase; j0 < jend; j0 += TJ) {
        __syncthreads();   // previous GEMM done with PsT/Whs/ed_s

        {   // stage Wh tile + ed tile
            const float4* src = (const float4*)(Whb + (size_t)(j0 + lr) * F_OUT);
            float4* dst = (float4*)&Whs[lr][0];
#pragma unroll
            for (int q = 0; q < 4; q++) dst[lp * 4 + q] = src[lp * 4 + q];
            if (t < 16) ((float4*)ed_s)[t] = ((const float4*)(edb + j0))[t];
        }
        __syncthreads();

        // P tile (transposed+swizzled) + partial row sums, from prefetched av
        float psum = 0.f;
#pragma unroll
        for (int q = 0; q < 4; q++) {
            int4 a4 = av[q];
            int jb  = jq * 16 + q * 4;
            int col = pi ^ jb;
            float e, p0, p1, p2, p3;
            e = esi + ed_s[jb + 0]; e = (e > 0.f) ? e : ALPHA * e; p0 = a4.x ? __expf(e) : 0.f;
            e = esi + ed_s[jb + 1]; e = (e > 0.f) ? e : ALPHA * e; p1 = a4.y ? __expf(e) : 0.f;
            e = esi + ed_s[jb + 2]; e = (e > 0.f) ? e : ALPHA * e; p2 = a4.z ? __expf(e) : 0.f;
            e = esi + ed_s[jb + 3]; e = (e > 0.f) ? e : ALPHA * e; p3 = a4.w ? __expf(e) : 0.f;
            psum += p0 + p1 + p2 + p3;
            PsT[jb + 0][col] = p0;
            PsT[jb + 1][col] = p1;
            PsT[jb + 2][col] = p2;
            PsT[jb + 3][col] = p3;
        }
        // prefetch adj for next tile (wrap to jbase on last iter; harmless)
        {
            int jn = (j0 + TJ < jend) ? j0 + TJ : jbase;
#pragma unroll
            for (int q = 0; q < 4; q++) av[q] = arow[(jn >> 2) + jq * 4 + q];
        }
        psum += __shfl_xor_sync(0xFFFFFFFFu, psum, 1);
        psum += __shfl_xor_sync(0xFFFFFFFFu, psum, 2);
        if (jq == 0) rowsum[pi] += psum;
        __syncthreads();

        // acc += P @ Whs  (64x64x64), all-LDS.128 + FFMA2
#pragma unroll 16
        for (int k = 0; k < TJ; k++) {
            float4 pv = *(const float4*)&PsT[k][(ty * 4) ^ (k & 0x3C)];
            ulonglong2 bv = *(const ulonglong2*)&Whs[k][tx * 4];
            ull a0 = pack2(pv.x), a1 = pack2(pv.y), a2 = pack2(pv.z), a3 = pack2(pv.w);
            fma2(acc[0][0], a0, bv.x); fma2(acc[0][1], a0, bv.y);
            fma2(acc[1][0], a1, bv.x); fma2(acc[1][1], a1, bv.y);
            fma2(acc[2][0], a2, bv.x); fma2(acc[2][1], a2, bv.y);
            fma2(acc[3][0], a3, bv.x); fma2(acc[3][1], a3, bv.y);
        }
    }
    __syncthreads();

    // write unnormalized partials + partial rowsums
    float* pacc = g_pacc + (((size_t)split * Bd + b) * Nd + i0) * F_OUT;
#pragma unroll
    for (int m = 0; m < 4; m++) {
        float4 o;
        unpack2(o.x, o.y, acc[m][0]);
        unpack2(o.z, o.w, acc[m][1]);
        *(float4*)(pacc + (size_t)(ty * 4 + m) * F_OUT + tx * 4) = o;
    }
    if (t < TI) g_prs[((size_t)split * Bd + b) * Nd + i0 + t] = rowsum[t];
}

// ---------------------------------------------------------------------------
// Kernel 3: sum the split partials, normalize, ELU, store.
// ---------------------------------------------------------------------------
__global__ __launch_bounds__(256) void reduce_kernel(float* __restrict__ out) {
    int tid = blockIdx.x * 256 + threadIdx.x;   // 0 .. B*N*16-1
    int row = tid >> 4;                          // b*N + i
    int c4  = tid & 15;

    float4 s = make_float4(0.f, 0.f, 0.f, 0.f);
    float rs = 0.f;
#pragma unroll
    for (int sp = 0; sp < SPLIT; sp++) {
        float4 v = *(const float4*)(g_pacc + ((size_t)sp * Bd * Nd + row) * F_OUT + c4 * 4);
        s.x += v.x; s.y += v.y; s.z += v.z; s.w += v.w;
        rs += g_prs[(size_t)sp * Bd * Nd + row];
    }
    float inv = 1.0f / rs;
    float4 o; float v;
    v = s.x * inv; o.x = (v > 0.f) ? v : expm1f(v);
    v = s.y * inv; o.y = (v > 0.f) ? v : expm1f(v);
    v = s.z * inv; o.z = (v > 0.f) ? v : expm1f(v);
    v = s.w * inv; o.w = (v > 0.f) ? v : expm1f(v);
    *(float4*)(out + (size_t)row * F_OUT + c4 * 4) = o;
}

// ---------------------------------------------------------------------------
extern "C" void kernel_launch(void* const* d_in, const int* in_sizes, int n_in,
                              void* d_out, int out_size) {
    const float* h   = (const float*)d_in[0];   // (8,2048,256) f32
    const int*   adj = (const int*)d_in[1];     // (8,2048,2048) i32
    const float* W   = (const float*)d_in[2];   // (256,64) f32
    const float* a   = (const float*)d_in[3];   // (128,1) f32
    float* out = (float*)d_out;                 // (8,2048,64) f32

    wh_kernel<<<Bd * Nd / 64, 256>>>(h, W, a);
    dim3 grid(Nd / TI, Bd, SPLIT);
    gat_kernel<<<grid, 256>>>(adj);
    reduce_kernel<<<Bd * Nd * 16 / 256, 256>>>(out);
}